// round 14
// baseline (speedup 1.0000x reference)
#include <cuda_runtime.h>
#include <cuda_bf16.h>
#include <stdint.h>

// Edge MLP, factored: h1[e] = relu(P[src]+Q'[dst]); P=node@W1[:64], Q'=node@W1[64:]+b1.
// R14: R11 structure + 384 threads (8 MMA warps, 4 producer warps) -> 24 warps/SM at 2 CTA/SM.
// MMA warps process their 64-col N-half as 2 serial 32-col chunks (acc 32 regs, no spills).

#define TILE_M 128
#define SW 136
#define SWA 72
#define THREADS 384
#define MAX_NODES 100352

__device__ __nv_bfloat16 g_P[(size_t)MAX_NODES * 128];
__device__ __nv_bfloat16 g_Q[(size_t)MAX_NODES * 128];

__device__ __forceinline__ unsigned pack_bf16(float lo, float hi) {
    unsigned r;
    asm("cvt.rn.bf16x2.f32 %0, %1, %2;" : "=r"(r) : "f"(hi), "f"(lo));
    return r;
}
__device__ __forceinline__ unsigned add2relu(unsigned a, unsigned b) {
    unsigned r;
    asm("add.rn.bf16x2 %0, %1, %2;" : "=r"(r) : "r"(a), "r"(b));
    asm("max.bf16x2 %0, %0, %1;" : "+r"(r) : "r"(0u));
    return r;
}
__device__ __forceinline__ void mma16816(float c[4],
                                         unsigned a0, unsigned a1, unsigned a2, unsigned a3,
                                         unsigned b0, unsigned b1) {
    asm volatile(
        "mma.sync.aligned.m16n8k16.row.col.f32.bf16.bf16.f32 "
        "{%0,%1,%2,%3}, {%4,%5,%6,%7}, {%8,%9}, {%0,%1,%2,%3};\n"
        : "+f"(c[0]), "+f"(c[1]), "+f"(c[2]), "+f"(c[3])
        : "r"(a0), "r"(a1), "r"(a2), "r"(a3), "r"(b0), "r"(b1));
}
__device__ __forceinline__ void ldsm4(unsigned r[4], uint32_t addr) {
    asm volatile("ldmatrix.sync.aligned.m8n8.x4.shared.b16 {%0,%1,%2,%3}, [%4];"
                 : "=r"(r[0]), "=r"(r[1]), "=r"(r[2]), "=r"(r[3]) : "r"(addr));
}

// ---------------- precompute (R11, proven): P = node@W1[:64], Q = node@W1[64:] + b1 ----
#define PQ_W1    0
#define PQ_A     34816
#define PQ_STAGE (PQ_A + 128 * SWA * 2)
#define PQ_B1    (PQ_STAGE + 128 * SW * 2)
#define PQ_SMEM  (PQ_B1 + 512)

extern "C" __global__ void __launch_bounds__(128, 2)
pq_precompute(const float* __restrict__ node_rep, const float* __restrict__ W1,
              const float* __restrict__ b1, int N, int ntiles) {
    extern __shared__ char smem_raw[];
    __nv_bfloat16* w1t   = reinterpret_cast<__nv_bfloat16*>(smem_raw + PQ_W1);
    __nv_bfloat16* a     = reinterpret_cast<__nv_bfloat16*>(smem_raw + PQ_A);
    __nv_bfloat16* stage = reinterpret_cast<__nv_bfloat16*>(smem_raw + PQ_STAGE);
    float* b1s = reinterpret_cast<float*>(smem_raw + PQ_B1);

    const int tid  = threadIdx.x;
    const int lane = tid & 31;
    const int warp = tid >> 5;

    for (int i = tid; i < 128 * 128; i += 128) {
        int k = i >> 7, n = i & 127;
        w1t[n * SW + k] = __float2bfloat16(W1[i]);
    }
    if (tid < 128) b1s[tid] = b1[tid];
    __syncthreads();

    const int q  = lane & 3;
    const int g4 = lane >> 2;
    const int r0 = (warp << 5) + g4;

    for (int tile = blockIdx.x; tile < ntiles; tile += gridDim.x) {
        const int base = tile * 128;

        for (int idx = tid; idx < 128 * 16; idx += 128) {
            const int row = idx >> 4, seg = idx & 15;
            int node = base + row; if (node >= N) node = N - 1;
            const float4 v = reinterpret_cast<const float4*>(node_rep + (long long)node * 64)[seg];
            uint64_t dv = ((uint64_t)pack_bf16(v.z, v.w) << 32) | pack_bf16(v.x, v.y);
            *reinterpret_cast<uint64_t*>(a + row * SWA + seg * 4) = dv;
        }
        __syncthreads();

        #pragma unroll
        for (int h = 0; h < 2; h++) {
            float acc[2][16][4];
            #pragma unroll
            for (int b = 0; b < 2; b++)
                #pragma unroll
                for (int t = 0; t < 16; t++)
                    #pragma unroll
                    for (int j = 0; j < 4; j++) acc[b][t][j] = 0.f;

            #pragma unroll
            for (int kt = 0; kt < 4; kt++) {
                const int kc = kt * 16 + 2 * q;
                unsigned af[2][4];
                #pragma unroll
                for (int b = 0; b < 2; b++) {
                    const int rb = r0 + 16 * b;
                    af[b][0] = *reinterpret_cast<const unsigned*>(a + rb * SWA + kc);
                    af[b][1] = *reinterpret_cast<const unsigned*>(a + (rb + 8) * SWA + kc);
                    af[b][2] = *reinterpret_cast<const unsigned*>(a + rb * SWA + kc + 8);
                    af[b][3] = *reinterpret_cast<const unsigned*>(a + (rb + 8) * SWA + kc + 8);
                }
                #pragma unroll
                for (int t = 0; t < 16; t++) {
                    const int n = t * 8 + g4;
                    const unsigned b0 = *reinterpret_cast<const unsigned*>(w1t + n * SW + 64 * h + kc);
                    const unsigned b1r = *reinterpret_cast<const unsigned*>(w1t + n * SW + 64 * h + kc + 8);
                    mma16816(acc[0][t], af[0][0], af[0][1], af[0][2], af[0][3], b0, b1r);
                    mma16816(acc[1][t], af[1][0], af[1][1], af[1][2], af[1][3], b0, b1r);
                }
            }

            const float bsc = h ? 1.f : 0.f;
            #pragma unroll
            for (int b = 0; b < 2; b++) {
                const int rr = r0 + 16 * b;
                #pragma unroll
                for (int t = 0; t < 16; t++) {
                    const int c = t * 8 + 2 * q;
                    const float bl = bsc * b1s[c], bh = bsc * b1s[c + 1];
                    *reinterpret_cast<unsigned*>(stage + rr * SW + c) =
                        pack_bf16(acc[b][t][0] + bl, acc[b][t][1] + bh);
                    *reinterpret_cast<unsigned*>(stage + (rr + 8) * SW + c) =
                        pack_bf16(acc[b][t][2] + bl, acc[b][t][3] + bh);
                }
            }
            __syncthreads();

            __nv_bfloat16* outp = h ? g_Q : g_P;
            for (int idx = tid; idx < 128 * 16; idx += 128) {
                const int row = idx >> 4, seg = idx & 15;
                if (base + row < N) {
                    const uint4 v = *reinterpret_cast<const uint4*>(stage + row * SW + seg * 8);
                    *reinterpret_cast<uint4*>(outp + (long long)(base + row) * 128 + seg * 8) = v;
                }
            }
            __syncthreads();
        }
    }
}

// ---------------- main ----------------
#define SM_W2    0
#define SM_FEAT0 34816
#define SM_FEAT1 (34816 + 32768)
#define SM_F32   (34816 + 65536)
#define SM_DD    (SM_F32 + 1024)
#define SMEM_BYTES (SM_DD + 2048)          // 103.5 KB -> 2 CTAs/SM, 24 warps

__device__ __forceinline__ uint32_t feat_addr(uint32_t fbase, int row, int gran) {
    return fbase + (uint32_t)row * 256u + (uint32_t)((gran ^ (row & 7)) << 4);
}
__device__ __forceinline__ uint32_t smem_u32(const void* p) {
    uint32_t a;
    asm("{ .reg .u64 t; cvta.to.shared.u64 t, %1; cvt.u32.u64 %0, t; }" : "=r"(a) : "l"(p));
    return a;
}

// 1 thread = 1 edge-half (128 B of the h1 row), batched uint4 loads
__device__ __forceinline__ void produce_half(uint32_t fbase, int base, int E,
                                             const int* __restrict__ eidx,
                                             int edge, int h) {
    const int e = base + edge;
    int src = 0, dst = 0;
    if (e < E) { src = eidx[e]; dst = eidx[E + e]; }
    const uint4* Pp = reinterpret_cast<const uint4*>(g_P + (long long)src * 128) + 8 * h;
    const uint4* Qp = reinterpret_cast<const uint4*>(g_Q + (long long)dst * 128) + 8 * h;
    #pragma unroll
    for (int i = 0; i < 8; i += 2) {
        const uint4 p0 = Pp[i], p1 = Pp[i + 1];
        const uint4 q0 = Qp[i], q1 = Qp[i + 1];
        uint4 o0, o1;
        o0.x = add2relu(p0.x, q0.x); o0.y = add2relu(p0.y, q0.y);
        o0.z = add2relu(p0.z, q0.z); o0.w = add2relu(p0.w, q0.w);
        o1.x = add2relu(p1.x, q1.x); o1.y = add2relu(p1.y, q1.y);
        o1.z = add2relu(p1.z, q1.z); o1.w = add2relu(p1.w, q1.w);
        const uint32_t a0 = feat_addr(fbase, edge, 8 * h + i);
        const uint32_t a1 = feat_addr(fbase, edge, 8 * h + i + 1);
        asm volatile("st.shared.v4.b32 [%0], {%1,%2,%3,%4};"
                     :: "r"(a0), "r"(o0.x), "r"(o0.y), "r"(o0.z), "r"(o0.w) : "memory");
        asm volatile("st.shared.v4.b32 [%0], {%1,%2,%3,%4};"
                     :: "r"(a1), "r"(o1.x), "r"(o1.y), "r"(o1.z), "r"(o1.w) : "memory");
    }
}

extern "C" __global__ void __launch_bounds__(THREADS, 2)
graphormer_edge_mlp(const int* __restrict__ eidx,
                    const float* __restrict__ W2, const float* __restrict__ b2,
                    const float* __restrict__ W3, const float* __restrict__ b3,
                    float* __restrict__ out,
                    int E, int num_tiles) {
    extern __shared__ char smem_raw[];
    __nv_bfloat16* w2t = reinterpret_cast<__nv_bfloat16*>(smem_raw + SM_W2);
    float* b2s = reinterpret_cast<float*>(smem_raw + SM_F32);
    float* w3s = b2s + 128;
    float* ddf = reinterpret_cast<float*>(smem_raw + SM_DD);   // [2 buf][2 half][128 rows]
    const uint32_t sb = smem_u32(smem_raw);
    const uint32_t fb[2] = { sb + SM_FEAT0, sb + SM_FEAT1 };
    const uint32_t wb = sb + SM_W2;

    const int tid  = threadIdx.x;
    const int lane = tid & 31;
    const int wid  = tid >> 5;

    for (int i = tid; i < 128 * 128; i += THREADS) {
        int k = i >> 7, n = i & 127;
        w2t[n * SW + k] = __float2bfloat16(W2[i]);
    }
    if (tid < 128) { b2s[tid] = b2[tid]; w3s[tid] = W3[tid]; }
    const float bb3 = b3[0];

    const bool is_prod = (wid >= 8);
    const int ptid = tid - 256;           // producer-local 0..127

    const int q  = lane & 3;
    const int g4 = lane >> 2;
    const int mwarp = wid & 3;
    const int r0blk = mwarp << 5;         // 32-row block
    const int r0 = r0blk + g4;
    const int half = (wid >> 2) & 1;      // N-half for MMA warps 0-7

    // LDSM addressing
    const int arow = lane & 15;
    const int ghi  = lane >> 4;
    const int ax   = arow & 7;
    const uint32_t arow0 = (uint32_t)(r0blk + arow) * 256u;
    const uint32_t arow1 = (uint32_t)(r0blk + 16 + arow) * 256u;
    uint32_t bbase[2][2];                 // [chunk][j]
    #pragma unroll
    for (int cq = 0; cq < 2; cq++)
        #pragma unroll
        for (int j = 0; j < 2; j++) {
            const int n = (half * 8 + cq * 4 + 2 * j + ghi) * 8 + (lane & 7);
            bbase[cq][j] = wb + (uint32_t)n * (SW * 2) + (uint32_t)(((lane >> 3) & 1) * 16);
        }

    __syncthreads();
    if (is_prod) {
        produce_half(fb[0], blockIdx.x * TILE_M, E, eidx, ptid >> 1, ptid & 1);
        produce_half(fb[0], blockIdx.x * TILE_M, E, eidx, (ptid + 128) >> 1, (ptid + 128) & 1);
    }
    __syncthreads();

    int buf = 0;
    int prev_base = -1;
    for (int tile = blockIdx.x; tile < num_tiles; tile += gridDim.x) {
        const int base = tile * TILE_M;

        // finalize previous tile (MMA warps 0-3 lanes = tid<128)
        if (tid < 128 && prev_base >= 0) {
            const int e = prev_base + tid;
            if (e < E) {
                const float d = ddf[(buf ^ 1) * 256 + tid] + ddf[(buf ^ 1) * 256 + 128 + tid];
                out[e] = 1.f / (1.f + __expf(-(d + bb3)));
            }
        }

        if (!is_prod) {
            // ---- GEMM: rows r0blk..+31, own N-half, 2 serial 32-col chunks ----
            const uint32_t f = fb[buf];
            float d0 = 0.f, d1 = 0.f;      // rows r0,(+8) block0 ; d2,d3 block1
            float d2 = 0.f, d3 = 0.f;
            #pragma unroll
            for (int cq = 0; cq < 2; cq++) {
                float acc[2][2][4];        // [row-block][n-tile-pair j]... 2x2 pairs -> 4 nt
                float acc2[2][2][4];
                #pragma unroll
                for (int b = 0; b < 2; b++)
                    #pragma unroll
                    for (int j = 0; j < 2; j++)
                        #pragma unroll
                        for (int x = 0; x < 4; x++) { acc[b][j][x] = 0.f; acc2[b][j][x] = 0.f; }

                #pragma unroll
                for (int kt = 0; kt < 8; kt++) {
                    const uint32_t goff = (uint32_t)(((2 * kt + ghi) ^ ax) << 4);
                    unsigned a0[4], a1[4];
                    ldsm4(a0, f + arow0 + goff);
                    ldsm4(a1, f + arow1 + goff);
                    #pragma unroll
                    for (int j = 0; j < 2; j++) {
                        unsigned bbr[4];
                        ldsm4(bbr, bbase[cq][j] + kt * 32);
                        mma16816(acc[0][j],  a0[0], a0[1], a0[2], a0[3], bbr[0], bbr[1]);
                        mma16816(acc[1][j],  a1[0], a1[1], a1[2], a1[3], bbr[0], bbr[1]);
                        mma16816(acc2[0][j], a0[0], a0[1], a0[2], a0[3], bbr[2], bbr[3]);
                        mma16816(acc2[1][j], a1[0], a1[1], a1[2], a1[3], bbr[2], bbr[3]);
                    }
                }

                // partial dot for this chunk: n-tiles (half*8 + cq*4 + {2j+ghi-ish})
                // acc[b][j] covers n-tile (…+2j), acc2[b][j] covers (…+2j+1)
                #pragma unroll
                for (int j = 0; j < 2; j++) {
                    const int c0 = (half * 8 + cq * 4 + 2 * j) * 8 + 2 * q;
                    const int c1 = c0 + 8;
                    const float wa0 = w3s[c0], wb0 = w3s[c0 + 1];
                    const float wa1 = w3s[c1], wb1 = w3s[c1 + 1];
                    d0 += fmaxf(acc[0][j][0]  + b2s[c0], 0.f) * wa0
                        + fmaxf(acc[0][j][1]  + b2s[c0 + 1], 0.f) * wb0
                        + fmaxf(acc2[0][j][0] + b2s[c1], 0.f) * wa1
                        + fmaxf(acc2[0][j][1] + b2s[c1 + 1], 0.f) * wb1;
                    d1 += fmaxf(acc[0][j][2]  + b2s[c0], 0.f) * wa0
                        + fmaxf(acc[0][j][3]  + b2s[c0 + 1], 0.f) * wb0
                        + fmaxf(acc2[0][j][2] + b2s[c1], 0.f) * wa1
                        + fmaxf(acc2[0][j][3] + b2s[c1 + 1], 0.f) * wb1;
                    d2 += fmaxf(acc[1][j][0]  + b2s[c0], 0.f) * wa0
                        + fmaxf(acc[1][j][1]  + b2s[c0 + 1], 0.f) * wb0
                        + fmaxf(acc2[1][j][0] + b2s[c1], 0.f) * wa1
                        + fmaxf(acc2[1][j][1] + b2s[c1 + 1], 0.f) * wb1;
                    d3 += fmaxf(acc[1][j][2]  + b2s[c0], 0.f) * wa0
                        + fmaxf(acc[1][j][3]  + b2s[c0 + 1], 0.f) * wb0
                        + fmaxf(acc2[1][j][2] + b2s[c1], 0.f) * wa1
                        + fmaxf(acc2[1][j][3] + b2s[c1 + 1], 0.f) * wb1;
                }
            }

            d0 += __shfl_xor_sync(0xFFFFFFFFu, d0, 1);
            d0 += __shfl_xor_sync(0xFFFFFFFFu, d0, 2);
            d1 += __shfl_xor_sync(0xFFFFFFFFu, d1, 1);
            d1 += __shfl_xor_sync(0xFFFFFFFFu, d1, 2);
            d2 += __shfl_xor_sync(0xFFFFFFFFu, d2, 1);
            d2 += __shfl_xor_sync(0xFFFFFFFFu, d2, 2);
            d3 += __shfl_xor_sync(0xFFFFFFFFu, d3, 1);
            d3 += __shfl_xor_sync(0xFFFFFFFFu, d3, 2);
            if (q == 0) {
                ddf[buf * 256 + half * 128 + r0]          = d0;
                ddf[buf * 256 + half * 128 + r0 + 8]      = d1;
                ddf[buf * 256 + half * 128 + r0 + 16]     = d2;
                ddf[buf * 256 + half * 128 + r0 + 24]     = d3;
            }
        } else {
            // ---- producers: gather next tile into other buffer ----
            const int ntile = tile + gridDim.x;
            if (ntile < num_tiles) {
                produce_half(fb[buf ^ 1], ntile * TILE_M, E, eidx, ptid >> 1, ptid & 1);
                produce_half(fb[buf ^ 1], ntile * TILE_M, E, eidx, (ptid + 128) >> 1, (ptid + 128) & 1);
            }
        }

        __syncthreads();
        prev_base = base;
        buf ^= 1;
    }

    if (tid < 128 && prev_base >= 0) {
        const int e = prev_base + tid;
        if (e < E) {
            const float d = ddf[(buf ^ 1) * 256 + tid] + ddf[(buf ^ 1) * 256 + 128 + tid];
            out[e] = 1.f / (1.f + __expf(-(d + bb3)));
        }
    }
}

extern "C" void kernel_launch(void* const* d_in, const int* in_sizes, int n_in,
                              void* d_out, int out_size) {
    const float* node_rep = (const float*)d_in[0];
    const int*   eidx     = (const int*)d_in[1];
    const float* W1       = (const float*)d_in[2];
    const float* b1       = (const float*)d_in[3];
    const float* W2       = (const float*)d_in[4];
    const float* b2       = (const float*)d_in[5];
    const float* W3       = (const float*)d_in[6];
    const float* b3       = (const float*)d_in[7];
    float*       out      = (float*)d_out;

    const int N = in_sizes[0] / 64;
    const int E = in_sizes[1] / 2;
    const int ntiles_pq = (N + 127) / 128;
    const int num_tiles = (E + TILE_M - 1) / TILE_M;

    cudaFuncSetAttribute(pq_precompute,
                         cudaFuncAttributeMaxDynamicSharedMemorySize, PQ_SMEM);
    cudaFuncSetAttribute(graphormer_edge_mlp,
                         cudaFuncAttributeMaxDynamicSharedMemorySize, SMEM_BYTES);

    int g1 = ntiles_pq < 296 ? ntiles_pq : 296;
    pq_precompute<<<g1, 128, PQ_SMEM>>>(node_rep, W1, b1, N, ntiles_pq);

    int g2 = num_tiles < 296 ? num_tiles : 296;
    graphormer_edge_mlp<<<g2, THREADS, SMEM_BYTES>>>(
        eidx, W2, b2, W3, b3, out, E, num_tiles);
}

// round 15
// speedup vs baseline: 2.2001x; 2.2001x over previous
#include <cuda_runtime.h>
#include <cuda_bf16.h>
#include <stdint.h>

// Edge MLP, factored: h1[e] = relu(P[src]+Q'[dst]); P=node@W1[:64], Q'=node@W1[64:]+b1.
// R15: main kernel = exact R11 (proven best). Precompute split by h across CTAs
// (grid 592; each CTA does one W1-half) -> half the per-CTA serial path.

#define TILE_M 128
#define SW 136
#define SWA 72
#define THREADS 256
#define MAX_NODES 100352

__device__ __nv_bfloat16 g_P[(size_t)MAX_NODES * 128];
__device__ __nv_bfloat16 g_Q[(size_t)MAX_NODES * 128];

__device__ __forceinline__ unsigned pack_bf16(float lo, float hi) {
    unsigned r;
    asm("cvt.rn.bf16x2.f32 %0, %1, %2;" : "=r"(r) : "f"(hi), "f"(lo));
    return r;
}
__device__ __forceinline__ unsigned add2relu(unsigned a, unsigned b) {
    unsigned r;
    asm("add.rn.bf16x2 %0, %1, %2;" : "=r"(r) : "r"(a), "r"(b));
    asm("max.bf16x2 %0, %0, %1;" : "+r"(r) : "r"(0u));
    return r;
}
__device__ __forceinline__ void mma16816(float c[4],
                                         unsigned a0, unsigned a1, unsigned a2, unsigned a3,
                                         unsigned b0, unsigned b1) {
    asm volatile(
        "mma.sync.aligned.m16n8k16.row.col.f32.bf16.bf16.f32 "
        "{%0,%1,%2,%3}, {%4,%5,%6,%7}, {%8,%9}, {%0,%1,%2,%3};\n"
        : "+f"(c[0]), "+f"(c[1]), "+f"(c[2]), "+f"(c[3])
        : "r"(a0), "r"(a1), "r"(a2), "r"(a3), "r"(b0), "r"(b1));
}
__device__ __forceinline__ void ldsm4(unsigned r[4], uint32_t addr) {
    asm volatile("ldmatrix.sync.aligned.m8n8.x4.shared.b16 {%0,%1,%2,%3}, [%4];"
                 : "=r"(r[0]), "=r"(r[1]), "=r"(r[2]), "=r"(r[3]) : "r"(addr));
}

// ---------------- precompute (split-h): CTA computes one of P (h=0) / Q (h=1) ----------
#define PQ_W1    0
#define PQ_A     34816
#define PQ_STAGE (PQ_A + 128 * SWA * 2)
#define PQ_B1    (PQ_STAGE + 128 * SW * 2)
#define PQ_SMEM  (PQ_B1 + 512)

extern "C" __global__ void __launch_bounds__(128, 2)
pq_precompute(const float* __restrict__ node_rep, const float* __restrict__ W1,
              const float* __restrict__ b1, int N, int ntiles) {
    extern __shared__ char smem_raw[];
    __nv_bfloat16* w1t   = reinterpret_cast<__nv_bfloat16*>(smem_raw + PQ_W1);
    __nv_bfloat16* a     = reinterpret_cast<__nv_bfloat16*>(smem_raw + PQ_A);
    __nv_bfloat16* stage = reinterpret_cast<__nv_bfloat16*>(smem_raw + PQ_STAGE);
    float* b1s = reinterpret_cast<float*>(smem_raw + PQ_B1);

    const int tid  = threadIdx.x;
    const int lane = tid & 31;
    const int warp = tid >> 5;

    const int h = blockIdx.x & 1;                 // which W1 half this CTA computes
    const int cta = blockIdx.x >> 1;
    const int cstride = gridDim.x >> 1;

    // load only the needed 64 k-rows of W1 (transposed)
    for (int i = tid; i < 128 * 64; i += 128) {
        const int k = i >> 7, n = i & 127;        // k 0..63 local
        w1t[n * SW + k] = __float2bfloat16(W1[(64 * h + k) * 128 + n]);
    }
    if (tid < 128) b1s[tid] = b1[tid];
    __syncthreads();

    const int q  = lane & 3;
    const int g4 = lane >> 2;
    const int r0 = (warp << 5) + g4;

    for (int tile = cta; tile < ntiles; tile += cstride) {
        const int base = tile * 128;

        for (int idx = tid; idx < 128 * 16; idx += 128) {
            const int row = idx >> 4, seg = idx & 15;
            int node = base + row; if (node >= N) node = N - 1;
            const float4 v = reinterpret_cast<const float4*>(node_rep + (long long)node * 64)[seg];
            uint64_t dv = ((uint64_t)pack_bf16(v.z, v.w) << 32) | pack_bf16(v.x, v.y);
            *reinterpret_cast<uint64_t*>(a + row * SWA + seg * 4) = dv;
        }
        __syncthreads();

        float acc[2][16][4];
        #pragma unroll
        for (int b = 0; b < 2; b++)
            #pragma unroll
            for (int t = 0; t < 16; t++)
                #pragma unroll
                for (int j = 0; j < 4; j++) acc[b][t][j] = 0.f;

        #pragma unroll
        for (int kt = 0; kt < 4; kt++) {
            const int kc = kt * 16 + 2 * q;
            unsigned af[2][4];
            #pragma unroll
            for (int b = 0; b < 2; b++) {
                const int rb = r0 + 16 * b;
                af[b][0] = *reinterpret_cast<const unsigned*>(a + rb * SWA + kc);
                af[b][1] = *reinterpret_cast<const unsigned*>(a + (rb + 8) * SWA + kc);
                af[b][2] = *reinterpret_cast<const unsigned*>(a + rb * SWA + kc + 8);
                af[b][3] = *reinterpret_cast<const unsigned*>(a + (rb + 8) * SWA + kc + 8);
            }
            #pragma unroll
            for (int t = 0; t < 16; t++) {
                const int n = t * 8 + g4;
                const unsigned b0 = *reinterpret_cast<const unsigned*>(w1t + n * SW + kc);
                const unsigned b1r = *reinterpret_cast<const unsigned*>(w1t + n * SW + kc + 8);
                mma16816(acc[0][t], af[0][0], af[0][1], af[0][2], af[0][3], b0, b1r);
                mma16816(acc[1][t], af[1][0], af[1][1], af[1][2], af[1][3], b0, b1r);
            }
        }

        const float bsc = h ? 1.f : 0.f;          // fold b1 into Q only
        #pragma unroll
        for (int b = 0; b < 2; b++) {
            const int rr = r0 + 16 * b;
            #pragma unroll
            for (int t = 0; t < 16; t++) {
                const int c = t * 8 + 2 * q;
                const float bl = bsc * b1s[c], bh = bsc * b1s[c + 1];
                *reinterpret_cast<unsigned*>(stage + rr * SW + c) =
                    pack_bf16(acc[b][t][0] + bl, acc[b][t][1] + bh);
                *reinterpret_cast<unsigned*>(stage + (rr + 8) * SW + c) =
                    pack_bf16(acc[b][t][2] + bl, acc[b][t][3] + bh);
            }
        }
        __syncthreads();

        __nv_bfloat16* outp = h ? g_Q : g_P;
        for (int idx = tid; idx < 128 * 16; idx += 128) {
            const int row = idx >> 4, seg = idx & 15;
            if (base + row < N) {
                const uint4 v = *reinterpret_cast<const uint4*>(stage + row * SW + seg * 8);
                *reinterpret_cast<uint4*>(outp + (long long)(base + row) * 128 + seg * 8) = v;
            }
        }
        __syncthreads();
    }
}

// ---------------- main (exact R11) ----------------
#define SM_W2    0
#define SM_FEAT0 34816
#define SM_FEAT1 (34816 + 32768)
#define SM_F32   (34816 + 65536)
#define SM_DD    (SM_F32 + 1024)
#define SMEM_BYTES (SM_DD + 2048)

__device__ __forceinline__ uint32_t feat_addr(uint32_t fbase, int row, int gran, int within) {
    return fbase + (uint32_t)row * 256u + (uint32_t)((gran ^ (row & 7)) << 4) + (uint32_t)within;
}
__device__ __forceinline__ uint32_t smem_u32(const void* p) {
    uint32_t a;
    asm("{ .reg .u64 t; cvta.to.shared.u64 t, %1; cvt.u32.u64 %0, t; }" : "=r"(a) : "l"(p));
    return a;
}

__device__ __forceinline__ void produce_tile(uint32_t fbase, int base, int E,
                                             const int* __restrict__ eidx,
                                             int grp, int l16) {
    #pragma unroll
    for (int half = 0; half < 2; half++) {
        int sidx[8], didx[8];
        #pragma unroll
        for (int i = 0; i < 8; i++) {
            const int e = base + grp + 8 * (half * 8 + i);
            const bool v = e < E;
            sidx[i] = v ? eidx[e] : 0;
            didx[i] = v ? eidx[E + e] : 0;
        }
        #pragma unroll
        for (int i = 0; i < 8; i++) {
            const int edge = grp + 8 * (half * 8 + i);
            const uint4 pv = reinterpret_cast<const uint4*>(g_P + (long long)sidx[i] * 128)[l16];
            const uint4 qv = reinterpret_cast<const uint4*>(g_Q + (long long)didx[i] * 128)[l16];
            uint4 o;
            o.x = add2relu(pv.x, qv.x); o.y = add2relu(pv.y, qv.y);
            o.z = add2relu(pv.z, qv.z); o.w = add2relu(pv.w, qv.w);
            const uint32_t ad = feat_addr(fbase, edge, l16, 0);
            asm volatile("st.shared.v4.b32 [%0], {%1,%2,%3,%4};"
                         :: "r"(ad), "r"(o.x), "r"(o.y), "r"(o.z), "r"(o.w) : "memory");
        }
    }
}

extern "C" __global__ void __launch_bounds__(THREADS, 2)
graphormer_edge_mlp(const int* __restrict__ eidx,
                    const float* __restrict__ W2, const float* __restrict__ b2,
                    const float* __restrict__ W3, const float* __restrict__ b3,
                    float* __restrict__ out,
                    int E, int num_tiles) {
    extern __shared__ char smem_raw[];
    __nv_bfloat16* w2t = reinterpret_cast<__nv_bfloat16*>(smem_raw + SM_W2);
    float* b2s = reinterpret_cast<float*>(smem_raw + SM_F32);
    float* w3s = b2s + 128;
    float* ddf = reinterpret_cast<float*>(smem_raw + SM_DD);
    const uint32_t sb = smem_u32(smem_raw);
    const uint32_t fb[2] = { sb + SM_FEAT0, sb + SM_FEAT1 };
    const uint32_t wb = sb + SM_W2;

    const int tid  = threadIdx.x;
    const int lane = tid & 31;
    const int wid  = tid >> 5;

    for (int i = tid; i < 128 * 128; i += THREADS) {
        int k = i >> 7, n = i & 127;
        w2t[n * SW + k] = __float2bfloat16(W2[i]);
    }
    if (tid < 128) { b2s[tid] = b2[tid]; w3s[tid] = W3[tid]; }
    const float bb3 = b3[0];

    const bool is_prod = (wid >= 4);
    const int ptid = tid - 128;
    const int grp = ptid >> 4, l16 = ptid & 15;

    const int q  = lane & 3;
    const int g4 = lane >> 2;
    const int mwarp = wid & 3;
    const int r0blk = mwarp << 5;
    const int r0 = r0blk + g4;
    const int ch = is_prod ? 1 : 0;

    const int arow = lane & 15;
    const int ghi  = lane >> 4;
    const int ax   = arow & 7;
    const uint32_t arow0 = (uint32_t)(r0blk + arow) * 256u;
    const uint32_t arow1 = (uint32_t)(r0blk + 16 + arow) * 256u;
    uint32_t bbase[4];
    #pragma unroll
    for (int j = 0; j < 4; j++) {
        const int n = (ch * 8 + 2 * j + ghi) * 8 + (lane & 7);
        bbase[j] = wb + (uint32_t)n * (SW * 2) + (uint32_t)(((lane >> 3) & 1) * 16);
    }

    __syncthreads();
    if (is_prod)
        produce_tile(fb[0], blockIdx.x * TILE_M, E, eidx, grp, l16);
    __syncthreads();

    int buf = 0;
    int prev_base = -1;
    for (int tile = blockIdx.x; tile < num_tiles; tile += gridDim.x) {
        const int base = tile * TILE_M;

        if (!is_prod && prev_base >= 0) {
            const int e = prev_base + tid;
            if (e < E) {
                const float d = ddf[(buf ^ 1) * 256 + tid] + ddf[(buf ^ 1) * 256 + 128 + tid];
                out[e] = 1.f / (1.f + __expf(-(d + bb3)));
            }
        }

        {
            const uint32_t f = fb[buf];
            float acc[2][8][4];
            #pragma unroll
            for (int b = 0; b < 2; b++)
                #pragma unroll
                for (int t = 0; t < 8; t++)
                    #pragma unroll
                    for (int j = 0; j < 4; j++) acc[b][t][j] = 0.f;

            #pragma unroll
            for (int kt = 0; kt < 8; kt++) {
                const uint32_t goff = (uint32_t)(((2 * kt + ghi) ^ ax) << 4);
                unsigned a[2][4];
                ldsm4(a[0], f + arow0 + goff);
                ldsm4(a[1], f + arow1 + goff);
                #pragma unroll
                for (int j = 0; j < 4; j++) {
                    unsigned bbr[4];
                    ldsm4(bbr, bbase[j] + kt * 32);
                    mma16816(acc[0][2 * j],     a[0][0], a[0][1], a[0][2], a[0][3], bbr[0], bbr[1]);
                    mma16816(acc[1][2 * j],     a[1][0], a[1][1], a[1][2], a[1][3], bbr[0], bbr[1]);
                    mma16816(acc[0][2 * j + 1], a[0][0], a[0][1], a[0][2], a[0][3], bbr[2], bbr[3]);
                    mma16816(acc[1][2 * j + 1], a[1][0], a[1][1], a[1][2], a[1][3], bbr[2], bbr[3]);
                }
            }

            #pragma unroll
            for (int b = 0; b < 2; b++) {
                float d0 = 0.f, d1 = 0.f;
                #pragma unroll
                for (int t = 0; t < 8; t++) {
                    const int c = (ch * 8 + t) * 8 + 2 * q;
                    const float wa = w3s[c], wbv = w3s[c + 1];
                    d0 += fmaxf(acc[b][t][0] + b2s[c], 0.f) * wa
                        + fmaxf(acc[b][t][1] + b2s[c + 1], 0.f) * wbv;
                    d1 += fmaxf(acc[b][t][2] + b2s[c], 0.f) * wa
                        + fmaxf(acc[b][t][3] + b2s[c + 1], 0.f) * wbv;
                }
                d0 += __shfl_xor_sync(0xFFFFFFFFu, d0, 1);
                d0 += __shfl_xor_sync(0xFFFFFFFFu, d0, 2);
                d1 += __shfl_xor_sync(0xFFFFFFFFu, d1, 1);
                d1 += __shfl_xor_sync(0xFFFFFFFFu, d1, 2);
                if (q == 0) {
                    ddf[buf * 256 + ch * 128 + r0 + 16 * b]     = d0;
                    ddf[buf * 256 + ch * 128 + r0 + 16 * b + 8] = d1;
                }
            }
        }

        if (is_prod) {
            const int ntile = tile + gridDim.x;
            if (ntile < num_tiles)
                produce_tile(fb[buf ^ 1], ntile * TILE_M, E, eidx, grp, l16);
        }

        __syncthreads();
        prev_base = base;
        buf ^= 1;
    }

    if (!is_prod && prev_base >= 0) {
        const int e = prev_base + tid;
        if (e < E) {
            const float d = ddf[(buf ^ 1) * 256 + tid] + ddf[(buf ^ 1) * 256 + 128 + tid];
            out[e] = 1.f / (1.f + __expf(-(d + bb3)));
        }
    }
}

extern "C" void kernel_launch(void* const* d_in, const int* in_sizes, int n_in,
                              void* d_out, int out_size) {
    const float* node_rep = (const float*)d_in[0];
    const int*   eidx     = (const int*)d_in[1];
    const float* W1       = (const float*)d_in[2];
    const float* b1       = (const float*)d_in[3];
    const float* W2       = (const float*)d_in[4];
    const float* b2       = (const float*)d_in[5];
    const float* W3       = (const float*)d_in[6];
    const float* b3       = (const float*)d_in[7];
    float*       out      = (float*)d_out;

    const int N = in_sizes[0] / 64;
    const int E = in_sizes[1] / 2;
    const int ntiles_pq = (N + 127) / 128;
    const int num_tiles = (E + TILE_M - 1) / TILE_M;

    cudaFuncSetAttribute(pq_precompute,
                         cudaFuncAttributeMaxDynamicSharedMemorySize, PQ_SMEM);
    cudaFuncSetAttribute(graphormer_edge_mlp,
                         cudaFuncAttributeMaxDynamicSharedMemorySize, SMEM_BYTES);

    int g1 = 2 * ntiles_pq < 592 ? 2 * ntiles_pq : 592;
    pq_precompute<<<g1, 128, PQ_SMEM>>>(node_rep, W1, b1, N, ntiles_pq);

    int g2 = num_tiles < 296 ? num_tiles : 296;
    graphormer_edge_mlp<<<g2, THREADS, SMEM_BYTES>>>(
        eidx, W2, b2, W3, b3, out, E, num_tiles);
}

// round 16
// speedup vs baseline: 2.2731x; 1.0332x over previous
#include <cuda_runtime.h>
#include <cuda_bf16.h>
#include <stdint.h>

// Edge MLP, factored: h1[e] = relu(P[src]+Q'[dst]); P=node@W1[:64], Q'=node@W1[64:]+b1.
// R16: main kernel = R11/R15 (proven, 136.8us). Precompute: combined-h per CTA again,
// W1 loaded via float4 (32 LDG.128/thread vs 128 scalar LDG) -> startup cost ~4x lower.

#define TILE_M 128
#define SW 136
#define SWA 72
#define THREADS 256
#define MAX_NODES 100352

__device__ __nv_bfloat16 g_P[(size_t)MAX_NODES * 128];
__device__ __nv_bfloat16 g_Q[(size_t)MAX_NODES * 128];

__device__ __forceinline__ unsigned pack_bf16(float lo, float hi) {
    unsigned r;
    asm("cvt.rn.bf16x2.f32 %0, %1, %2;" : "=r"(r) : "f"(hi), "f"(lo));
    return r;
}
__device__ __forceinline__ unsigned add2relu(unsigned a, unsigned b) {
    unsigned r;
    asm("add.rn.bf16x2 %0, %1, %2;" : "=r"(r) : "r"(a), "r"(b));
    asm("max.bf16x2 %0, %0, %1;" : "+r"(r) : "r"(0u));
    return r;
}
__device__ __forceinline__ void mma16816(float c[4],
                                         unsigned a0, unsigned a1, unsigned a2, unsigned a3,
                                         unsigned b0, unsigned b1) {
    asm volatile(
        "mma.sync.aligned.m16n8k16.row.col.f32.bf16.bf16.f32 "
        "{%0,%1,%2,%3}, {%4,%5,%6,%7}, {%8,%9}, {%0,%1,%2,%3};\n"
        : "+f"(c[0]), "+f"(c[1]), "+f"(c[2]), "+f"(c[3])
        : "r"(a0), "r"(a1), "r"(a2), "r"(a3), "r"(b0), "r"(b1));
}
__device__ __forceinline__ void ldsm4(unsigned r[4], uint32_t addr) {
    asm volatile("ldmatrix.sync.aligned.m8n8.x4.shared.b16 {%0,%1,%2,%3}, [%4];"
                 : "=r"(r[0]), "=r"(r[1]), "=r"(r[2]), "=r"(r[3]) : "r"(addr));
}

// ---------------- precompute: P = node@W1[:64], Q = node@W1[64:] + b1 ----------------
#define PQ_W1    0
#define PQ_A     34816
#define PQ_STAGE (PQ_A + 128 * SWA * 2)
#define PQ_B1    (PQ_STAGE + 128 * SW * 2)
#define PQ_SMEM  (PQ_B1 + 512)

extern "C" __global__ void __launch_bounds__(128, 2)
pq_precompute(const float* __restrict__ node_rep, const float* __restrict__ W1,
              const float* __restrict__ b1, int N, int ntiles) {
    extern __shared__ char smem_raw[];
    __nv_bfloat16* w1t   = reinterpret_cast<__nv_bfloat16*>(smem_raw + PQ_W1);
    __nv_bfloat16* a     = reinterpret_cast<__nv_bfloat16*>(smem_raw + PQ_A);
    __nv_bfloat16* stage = reinterpret_cast<__nv_bfloat16*>(smem_raw + PQ_STAGE);
    float* b1s = reinterpret_cast<float*>(smem_raw + PQ_B1);

    const int tid  = threadIdx.x;
    const int lane = tid & 31;
    const int warp = tid >> 5;

    // W1 -> transposed bf16 SMEM, float4 coalesced loads (32 LDG.128/thread)
    #pragma unroll 4
    for (int i = tid; i < 128 * 32; i += 128) {
        const int k  = i >> 5;
        const int nb = (i & 31) << 2;
        const float4 v = *reinterpret_cast<const float4*>(W1 + k * 128 + nb);
        w1t[(nb + 0) * SW + k] = __float2bfloat16(v.x);
        w1t[(nb + 1) * SW + k] = __float2bfloat16(v.y);
        w1t[(nb + 2) * SW + k] = __float2bfloat16(v.z);
        w1t[(nb + 3) * SW + k] = __float2bfloat16(v.w);
    }
    if (tid < 128) b1s[tid] = b1[tid];
    __syncthreads();

    const int q  = lane & 3;
    const int g4 = lane >> 2;
    const int r0 = (warp << 5) + g4;

    for (int tile = blockIdx.x; tile < ntiles; tile += gridDim.x) {
        const int base = tile * 128;

        for (int idx = tid; idx < 128 * 16; idx += 128) {
            const int row = idx >> 4, seg = idx & 15;
            int node = base + row; if (node >= N) node = N - 1;
            const float4 v = reinterpret_cast<const float4*>(node_rep + (long long)node * 64)[seg];
            uint64_t dv = ((uint64_t)pack_bf16(v.z, v.w) << 32) | pack_bf16(v.x, v.y);
            *reinterpret_cast<uint64_t*>(a + row * SWA + seg * 4) = dv;
        }
        __syncthreads();

        #pragma unroll
        for (int h = 0; h < 2; h++) {
            float acc[2][16][4];
            #pragma unroll
            for (int b = 0; b < 2; b++)
                #pragma unroll
                for (int t = 0; t < 16; t++)
                    #pragma unroll
                    for (int j = 0; j < 4; j++) acc[b][t][j] = 0.f;

            #pragma unroll
            for (int kt = 0; kt < 4; kt++) {
                const int kc = kt * 16 + 2 * q;
                unsigned af[2][4];
                #pragma unroll
                for (int b = 0; b < 2; b++) {
                    const int rb = r0 + 16 * b;
                    af[b][0] = *reinterpret_cast<const unsigned*>(a + rb * SWA + kc);
                    af[b][1] = *reinterpret_cast<const unsigned*>(a + (rb + 8) * SWA + kc);
                    af[b][2] = *reinterpret_cast<const unsigned*>(a + rb * SWA + kc + 8);
                    af[b][3] = *reinterpret_cast<const unsigned*>(a + (rb + 8) * SWA + kc + 8);
                }
                #pragma unroll
                for (int t = 0; t < 16; t++) {
                    const int n = t * 8 + g4;
                    const unsigned b0 = *reinterpret_cast<const unsigned*>(w1t + n * SW + 64 * h + kc);
                    const unsigned b1r = *reinterpret_cast<const unsigned*>(w1t + n * SW + 64 * h + kc + 8);
                    mma16816(acc[0][t], af[0][0], af[0][1], af[0][2], af[0][3], b0, b1r);
                    mma16816(acc[1][t], af[1][0], af[1][1], af[1][2], af[1][3], b0, b1r);
                }
            }

            const float bsc = h ? 1.f : 0.f;
            #pragma unroll
            for (int b = 0; b < 2; b++) {
                const int rr = r0 + 16 * b;
                #pragma unroll
                for (int t = 0; t < 16; t++) {
                    const int c = t * 8 + 2 * q;
                    const float bl = bsc * b1s[c], bh = bsc * b1s[c + 1];
                    *reinterpret_cast<unsigned*>(stage + rr * SW + c) =
                        pack_bf16(acc[b][t][0] + bl, acc[b][t][1] + bh);
                    *reinterpret_cast<unsigned*>(stage + (rr + 8) * SW + c) =
                        pack_bf16(acc[b][t][2] + bl, acc[b][t][3] + bh);
                }
            }
            __syncthreads();

            __nv_bfloat16* outp = h ? g_Q : g_P;
            for (int idx = tid; idx < 128 * 16; idx += 128) {
                const int row = idx >> 4, seg = idx & 15;
                if (base + row < N) {
                    const uint4 v = *reinterpret_cast<const uint4*>(stage + row * SW + seg * 8);
                    *reinterpret_cast<uint4*>(outp + (long long)(base + row) * 128 + seg * 8) = v;
                }
            }
            __syncthreads();
        }
    }
}

// ---------------- main (R11/R15 structure) ----------------
#define SM_W2    0
#define SM_FEAT0 34816
#define SM_FEAT1 (34816 + 32768)
#define SM_F32   (34816 + 65536)
#define SM_DD    (SM_F32 + 1024)
#define SMEM_BYTES (SM_DD + 2048)

__device__ __forceinline__ uint32_t feat_addr(uint32_t fbase, int row, int gran, int within) {
    return fbase + (uint32_t)row * 256u + (uint32_t)((gran ^ (row & 7)) << 4) + (uint32_t)within;
}
__device__ __forceinline__ uint32_t smem_u32(const void* p) {
    uint32_t a;
    asm("{ .reg .u64 t; cvta.to.shared.u64 t, %1; cvt.u32.u64 %0, t; }" : "=r"(a) : "l"(p));
    return a;
}

__device__ __forceinline__ void produce_tile(uint32_t fbase, int base, int E,
                                             const int* __restrict__ eidx,
                                             int grp, int l16) {
    #pragma unroll
    for (int half = 0; half < 2; half++) {
        int sidx[8], didx[8];
        #pragma unroll
        for (int i = 0; i < 8; i++) {
            const int e = base + grp + 8 * (half * 8 + i);
            const bool v = e < E;
            sidx[i] = v ? eidx[e] : 0;
            didx[i] = v ? eidx[E + e] : 0;
        }
        #pragma unroll
        for (int i = 0; i < 8; i++) {
            const int edge = grp + 8 * (half * 8 + i);
            const uint4 pv = reinterpret_cast<const uint4*>(g_P + (long long)sidx[i] * 128)[l16];
            const uint4 qv = reinterpret_cast<const uint4*>(g_Q + (long long)didx[i] * 128)[l16];
            uint4 o;
            o.x = add2relu(pv.x, qv.x); o.y = add2relu(pv.y, qv.y);
            o.z = add2relu(pv.z, qv.z); o.w = add2relu(pv.w, qv.w);
            const uint32_t ad = feat_addr(fbase, edge, l16, 0);
            asm volatile("st.shared.v4.b32 [%0], {%1,%2,%3,%4};"
                         :: "r"(ad), "r"(o.x), "r"(o.y), "r"(o.z), "r"(o.w) : "memory");
        }
    }
}

extern "C" __global__ void __launch_bounds__(THREADS, 2)
graphormer_edge_mlp(const int* __restrict__ eidx,
                    const float* __restrict__ W2, const float* __restrict__ b2,
                    const float* __restrict__ W3, const float* __restrict__ b3,
                    float* __restrict__ out,
                    int E, int num_tiles) {
    extern __shared__ char smem_raw[];
    __nv_bfloat16* w2t = reinterpret_cast<__nv_bfloat16*>(smem_raw + SM_W2);
    float* b2s = reinterpret_cast<float*>(smem_raw + SM_F32);
    float* w3s = b2s + 128;
    float* ddf = reinterpret_cast<float*>(smem_raw + SM_DD);
    const uint32_t sb = smem_u32(smem_raw);
    const uint32_t fb[2] = { sb + SM_FEAT0, sb + SM_FEAT1 };
    const uint32_t wb = sb + SM_W2;

    const int tid  = threadIdx.x;
    const int lane = tid & 31;
    const int wid  = tid >> 5;

    // W2 -> transposed bf16 SMEM, float4 coalesced (16 LDG.128/thread at 256 thr)
    #pragma unroll 4
    for (int i = tid; i < 128 * 32; i += THREADS) {
        const int k  = i >> 5;
        const int nb = (i & 31) << 2;
        const float4 v = *reinterpret_cast<const float4*>(W2 + k * 128 + nb);
        w2t[(nb + 0) * SW + k] = __float2bfloat16(v.x);
        w2t[(nb + 1) * SW + k] = __float2bfloat16(v.y);
        w2t[(nb + 2) * SW + k] = __float2bfloat16(v.z);
        w2t[(nb + 3) * SW + k] = __float2bfloat16(v.w);
    }
    if (tid < 128) { b2s[tid] = b2[tid]; w3s[tid] = W3[tid]; }
    const float bb3 = b3[0];

    const bool is_prod = (wid >= 4);
    const int ptid = tid - 128;
    const int grp = ptid >> 4, l16 = ptid & 15;

    const int q  = lane & 3;
    const int g4 = lane >> 2;
    const int mwarp = wid & 3;
    const int r0blk = mwarp << 5;
    const int r0 = r0blk + g4;
    const int ch = is_prod ? 1 : 0;

    const int arow = lane & 15;
    const int ghi  = lane >> 4;
    const int ax   = arow & 7;
    const uint32_t arow0 = (uint32_t)(r0blk + arow) * 256u;
    const uint32_t arow1 = (uint32_t)(r0blk + 16 + arow) * 256u;
    uint32_t bbase[4];
    #pragma unroll
    for (int j = 0; j < 4; j++) {
        const int n = (ch * 8 + 2 * j + ghi) * 8 + (lane & 7);
        bbase[j] = wb + (uint32_t)n * (SW * 2) + (uint32_t)(((lane >> 3) & 1) * 16);
    }

    __syncthreads();
    if (is_prod)
        produce_tile(fb[0], blockIdx.x * TILE_M, E, eidx, grp, l16);
    __syncthreads();

    int buf = 0;
    int prev_base = -1;
    for (int tile = blockIdx.x; tile < num_tiles; tile += gridDim.x) {
        const int base = tile * TILE_M;

        if (!is_prod && prev_base >= 0) {
            const int e = prev_base + tid;
            if (e < E) {
                const float d = ddf[(buf ^ 1) * 256 + tid] + ddf[(buf ^ 1) * 256 + 128 + tid];
                out[e] = 1.f / (1.f + __expf(-(d + bb3)));
            }
        }

        {
            const uint32_t f = fb[buf];
            float acc[2][8][4];
            #pragma unroll
            for (int b = 0; b < 2; b++)
                #pragma unroll
                for (int t = 0; t < 8; t++)
                    #pragma unroll
                    for (int j = 0; j < 4; j++) acc[b][t][j] = 0.f;

            #pragma unroll
            for (int kt = 0; kt < 8; kt++) {
                const uint32_t goff = (uint32_t)(((2 * kt + ghi) ^ ax) << 4);
                unsigned a[2][4];
                ldsm4(a[0], f + arow0 + goff);
                ldsm4(a[1], f + arow1 + goff);
                #pragma unroll
                for (int j = 0; j < 4; j++) {
                    unsigned bbr[4];
                    ldsm4(bbr, bbase[j] + kt * 32);
                    mma16816(acc[0][2 * j],     a[0][0], a[0][1], a[0][2], a[0][3], bbr[0], bbr[1]);
                    mma16816(acc[1][2 * j],     a[1][0], a[1][1], a[1][2], a[1][3], bbr[0], bbr[1]);
                    mma16816(acc[0][2 * j + 1], a[0][0], a[0][1], a[0][2], a[0][3], bbr[2], bbr[3]);
                    mma16816(acc[1][2 * j + 1], a[1][0], a[1][1], a[1][2], a[1][3], bbr[2], bbr[3]);
                }
            }

            #pragma unroll
            for (int b = 0; b < 2; b++) {
                float d0 = 0.f, d1 = 0.f;
                #pragma unroll
                for (int t = 0; t < 8; t++) {
                    const int c = (ch * 8 + t) * 8 + 2 * q;
                    const float wa = w3s[c], wbv = w3s[c + 1];
                    d0 += fmaxf(acc[b][t][0] + b2s[c], 0.f) * wa
                        + fmaxf(acc[b][t][1] + b2s[c + 1], 0.f) * wbv;
                    d1 += fmaxf(acc[b][t][2] + b2s[c], 0.f) * wa
                        + fmaxf(acc[b][t][3] + b2s[c + 1], 0.f) * wbv;
                }
                d0 += __shfl_xor_sync(0xFFFFFFFFu, d0, 1);
                d0 += __shfl_xor_sync(0xFFFFFFFFu, d0, 2);
                d1 += __shfl_xor_sync(0xFFFFFFFFu, d1, 1);
                d1 += __shfl_xor_sync(0xFFFFFFFFu, d1, 2);
                if (q == 0) {
                    ddf[buf * 256 + ch * 128 + r0 + 16 * b]     = d0;
                    ddf[buf * 256 + ch * 128 + r0 + 16 * b + 8] = d1;
                }
            }
        }

        if (is_prod) {
            const int ntile = tile + gridDim.x;
            if (ntile < num_tiles)
                produce_tile(fb[buf ^ 1], ntile * TILE_M, E, eidx, grp, l16);
        }

        __syncthreads();
        prev_base = base;
        buf ^= 1;
    }

    if (!is_prod && prev_base >= 0) {
        const int e = prev_base + tid;
        if (e < E) {
            const float d = ddf[(buf ^ 1) * 256 + tid] + ddf[(buf ^ 1) * 256 + 128 + tid];
            out[e] = 1.f / (1.f + __expf(-(d + bb3)));
        }
    }
}

extern "C" void kernel_launch(void* const* d_in, const int* in_sizes, int n_in,
                              void* d_out, int out_size) {
    const float* node_rep = (const float*)d_in[0];
    const int*   eidx     = (const int*)d_in[1];
    const float* W1       = (const float*)d_in[2];
    const float* b1       = (const float*)d_in[3];
    const float* W2       = (const float*)d_in[4];
    const float* b2       = (const float*)d_in[5];
    const float* W3       = (const float*)d_in[6];
    const float* b3       = (const float*)d_in[7];
    float*       out      = (float*)d_out;

    const int N = in_sizes[0] / 64;
    const int E = in_sizes[1] / 2;
    const int ntiles_pq = (N + 127) / 128;
    const int num_tiles = (E + TILE_M - 1) / TILE_M;

    cudaFuncSetAttribute(pq_precompute,
                         cudaFuncAttributeMaxDynamicSharedMemorySize, PQ_SMEM);
    cudaFuncSetAttribute(graphormer_edge_mlp,
                         cudaFuncAttributeMaxDynamicSharedMemorySize, SMEM_BYTES);

    int g1 = ntiles_pq < 296 ? ntiles_pq : 296;
    pq_precompute<<<g1, 128, PQ_SMEM>>>(node_rep, W1, b1, N, ntiles_pq);

    int g2 = num_tiles < 296 ? num_tiles : 296;
    graphormer_edge_mlp<<<g2, THREADS, SMEM_BYTES>>>(
        eidx, W2, b2, W3, b3, out, E, num_tiles);
}